// round 12
// baseline (speedup 1.0000x reference)
#include <cuda_runtime.h>
#include <cuda_bf16.h>
#include <cstdint>

// PatchEmbeder via mma.sync tf32 m16n8k8 + affine collapse.
// out[b,0,:]   = cls + pos[0]                                  (prep kernel)
// out[b,p+1,:] = x_patch @ W1 @ (W2@W3) + beff + pos[p+1]      (main kernel)
// x[b,p,k] = inputs[b, k/256, p, (k%256)/16, k%16]
// B=128, P=196 -> 25088 rows = 392 CTAs x 64 rows. K1=768, N1=32(=K2), E=768.
//
// R12 = R11 with the G1 consume bug fixed: the A-fragment base was missing the
// gr*RS2 row term (all lanes read staging row 0 -> rel_err 0.42).

#define THREADS 128
#define RS2     272              // G1 staging row stride bytes (68 words, ==4 mod 32)
#define BUF2    (16 * RS2)       // 4352 B per ring buffer
#define WSLOT   (4 * BUF2)       // 17408 B per warp
#define RSE     528              // epilogue tile row stride bytes (132 words)
#define OFFB    8448             // per-warp offset table (after 16*528 epilogue tile)

// ---- device scratch (rebuilt every replay by prep_kernel) ----
__device__ __align__(16) uint4 g_W1F [48 * 4 * 32];   // [kt16 48][nt 4][lane]
__device__ __align__(16) uint4 g_W23F[96 * 2 * 32];   // [nt 96][kt8-pair 2][lane]
__device__ __align__(16) float g_beff[768];

__device__ __forceinline__ uint32_t f2tf32(float f) {
    uint32_t r;
    asm("cvt.rna.tf32.f32 %0, %1;" : "=r"(r) : "f"(f));
    return r;
}
__device__ __forceinline__ void mma_tf32(float* c, const uint32_t a[4],
                                         uint32_t b0, uint32_t b1) {
    asm("mma.sync.aligned.m16n8k8.row.col.f32.tf32.tf32.f32 "
        "{%0,%1,%2,%3}, {%4,%5,%6,%7}, {%8,%9}, {%0,%1,%2,%3};"
        : "+f"(c[0]), "+f"(c[1]), "+f"(c[2]), "+f"(c[3])
        : "r"(a[0]), "r"(a[1]), "r"(a[2]), "r"(a[3]), "r"(b0), "r"(b1));
}
__device__ __forceinline__ uint32_t smem_u32(const void* p) {
    uint32_t a;
    asm("{ .reg .u64 t; cvta.to.shared.u64 t, %1; cvt.u32.u64 %0, t; }" : "=r"(a) : "l"(p));
    return a;
}
__device__ __forceinline__ void cp_async16(uint32_t dst, const void* src) {
    asm volatile("cp.async.cg.shared.global [%0], [%1], 16;" :: "r"(dst), "l"(src));
}
#define CP_COMMIT()  asm volatile("cp.async.commit_group;" ::: "memory")
#define CP_WAIT(N)   asm volatile("cp.async.wait_group %0;" :: "n"(N) : "memory")
__device__ __forceinline__ float lds32(uint32_t a) {
    float v;
    asm volatile("ld.shared.f32 %0, [%1];" : "=f"(v) : "r"(a));
    return v;
}
__device__ __forceinline__ void sts64(uint32_t a, float x, float y) {
    asm volatile("st.shared.v2.f32 [%0], {%1,%2};" :: "r"(a), "f"(x), "f"(y));
}
__device__ __forceinline__ void sts64i(uint32_t a, int x, int y) {
    asm volatile("st.shared.v2.u32 [%0], {%1,%2};" :: "r"(a), "r"(x), "r"(y));
}
__device__ __forceinline__ int2 lds64i(uint32_t a) {
    int2 v;
    asm volatile("ld.shared.v2.u32 {%0,%1}, [%2];" : "=r"(v.x), "=r"(v.y) : "r"(a));
    return v;
}
__device__ __forceinline__ float4 lds128(uint32_t a) {
    float4 v;
    asm volatile("ld.shared.v4.f32 {%0,%1,%2,%3}, [%4];"
                 : "=f"(v.x), "=f"(v.y), "=f"(v.z), "=f"(v.w) : "r"(a));
    return v;
}

// =====================================================================
// prep: bake W1 / W23=W2@W3 tf32 fragments, beff, cls rows.
// grid 192 x 128 = 24576 threads. W23 mapping puts lanes across e so
// W3 column reads are 128B-coalesced.
// =====================================================================
__global__ void prep_kernel(const float* __restrict__ W1, const float* __restrict__ b1,
                            const float* __restrict__ W2, const float* __restrict__ b2,
                            const float* __restrict__ W3, const float* __restrict__ b3,
                            const float* __restrict__ cls, const float* __restrict__ pos,
                            float* __restrict__ out)
{
    __shared__ float W2s[32 * 65];   // padded stride 65
    __shared__ float t1s[64];

    const int t = threadIdx.x;
    const int g = blockIdx.x * 128 + t;   // 0..24575

#pragma unroll
    for (int i = t; i < 2048; i += 128)
        W2s[(i >> 6) * 65 + (i & 63)] = __ldg(W2 + i);
    __syncthreads();

    if (t < 64) {
        float acc = __ldg(b2 + t);
#pragma unroll
        for (int i = 0; i < 32; ++i) acc += __ldg(b1 + i) * W2s[i * 65 + t];
        t1s[t] = acc;
    }
    __syncthreads();

    // ---- W1 fragment element (k = g>>5 in 0..767, n = g&31) ----
    {
        const int k = g >> 5, n = g & 31;
        const uint32_t tv = f2tf32(__ldg(W1 + k * 32 + n));
        const int kt16 = k >> 4;
        const int comp = (((k >> 3) & 1) << 1) | ((k & 7) >> 2);
        const int lane = ((n & 7) << 2) | (k & 3);
        const int nt = n >> 3;
        ((uint32_t*)&g_W1F[(kt16 * 4 + nt) * 32 + lane])[comp] = tv;
    }
    // ---- W23 fragment + beff: lanes span e -> W3 reads coalesced ----
    {
        const int e = g % 768, k2 = g / 768;
        float acc = 0.f;
        float accb = (k2 == 0) ? __ldg(b3 + e) : 0.f;
#pragma unroll
        for (int j = 0; j < 64; ++j) {
            const float w3v = __ldg(W3 + j * 768 + e);   // coalesced across lanes
            acc += W2s[k2 * 65 + j] * w3v;               // warp-uniform broadcast
            if (k2 == 0) accb += t1s[j] * w3v;
        }
        const uint32_t tv = f2tf32(acc);
        const int nt = e >> 3, pair = k2 >> 4;
        const int comp = (((k2 >> 3) & 1) << 1) | ((k2 & 7) >> 2);
        const int lane = ((e & 7) << 2) | (k2 & 3);
        ((uint32_t*)&g_W23F[(nt * 2 + pair) * 32 + lane])[comp] = tv;
        if (k2 == 0) g_beff[e] = accb;
    }
    // ---- cls rows ----
    {
        const int e4 = g % 192, b = g / 192;
        const float4 c = __ldg((const float4*)cls + e4);
        const float4 pp = __ldg((const float4*)pos + e4);
        *((float4*)(out + (size_t)b * 197 * 768) + e4) =
            make_float4(c.x + pp.x, c.y + pp.y, c.z + pp.z, c.w + pp.w);
    }
}

// =====================================================================
// main: 392 CTAs x 128 threads (4 warps), 64 rows. Warp w owns rows
// [w*16, w*16+16); zero CTA barriers. Per-warp depth-4 cp.async ring of
// 64-col fp32 X chunks; ring doubles as G23 result tile + offset table.
// =====================================================================
__global__ __launch_bounds__(THREADS, 3)
void patch_embed_mma(const float* __restrict__ X, const float* __restrict__ pos,
                     float* __restrict__ out)
{
    extern __shared__ char smem[];
    const uint32_t sb = smem_u32(smem);
    const int t = threadIdx.x;
    const int w = t >> 5;
    const int ln = t & 31;
    const int r0 = blockIdx.x * 64;
    const int wr0 = w << 4;                       // warp's 16 rows
    const uint32_t wbuf = sb + (uint32_t)w * WSLOT;

    const int gr = ln >> 2;                       // fragment row 0..7
    const int q2 = (ln & 3) << 1;                 // C-fragment col pair base

    // per-row gmem bases for this warp's 16 rows (channel offset added later)
    const float* rowbase[16];
#pragma unroll
    for (int lr = 0; lr < 16; ++lr) {
        const int R = r0 + wr0 + lr;
        const int b = R / 196;
        const int p = R - b * 196;
        rowbase[lr] = X + (((size_t)b * 3 * 196 + p) << 8);
    }

    // ---------------- G1: H[16x32] = Xrows @ W1, tf32, depth-4 ring ----------------
    float acc1[4][4];
#pragma unroll
    for (int i = 0; i < 4; ++i)
#pragma unroll
        for (int j = 0; j < 4; ++j) acc1[i][j] = 0.f;

    // stage 64-col chunk kc (0..11) into ring slot d: 8 its x 2 rows x 16B/lane
    auto stage = [&](int kc, int d) {
        const size_t choff = (size_t)(kc >> 2) * (196 << 8) + ((kc & 3) << 6) + ((ln & 15) << 2);
        const uint32_t dst = wbuf + (uint32_t)d * BUF2 + (uint32_t)((ln & 15) << 4);
        const int lr0 = ln >> 4;
#pragma unroll
        for (int it = 0; it < 8; ++it) {
            const int lr = (it << 1) + lr0;
            cp_async16(dst + (uint32_t)lr * RS2, rowbase[lr] + choff);
        }
        CP_COMMIT();
    };

    auto consume = [&](int kc, int d) {
        // BUGFIX vs R11: include the lane's fragment-row term gr*RS2.
        const uint32_t a0 = wbuf + (uint32_t)d * BUF2 + (uint32_t)gr * RS2
                          + (uint32_t)((ln & 3) << 2);
#pragma unroll
        for (int gq = 0; gq < 4; ++gq) {            // 4 kt16-groups per 64-col chunk
            const uint32_t ae = a0 + (uint32_t)(gq << 6);   // 16 floats per group
            uint32_t Ae[4], Ao[4];
            Ae[0] = f2tf32(lds32(ae));
            Ae[1] = f2tf32(lds32(ae + 8 * RS2));
            Ae[2] = f2tf32(lds32(ae + 16));
            Ae[3] = f2tf32(lds32(ae + 8 * RS2 + 16));
            Ao[0] = f2tf32(lds32(ae + 32));
            Ao[1] = f2tf32(lds32(ae + 8 * RS2 + 32));
            Ao[2] = f2tf32(lds32(ae + 48));
            Ao[3] = f2tf32(lds32(ae + 8 * RS2 + 48));

            const uint4* bp = &g_W1F[(((kc << 2) + gq) << 2) * 32 + ln];
            uint4 bf[4];
#pragma unroll
            for (int nt = 0; nt < 4; ++nt) bf[nt] = __ldg(bp + nt * 32);
#pragma unroll
            for (int nt = 0; nt < 4; ++nt) mma_tf32(acc1[nt], Ae, bf[nt].x, bf[nt].y);
#pragma unroll
            for (int nt = 0; nt < 4; ++nt) mma_tf32(acc1[nt], Ao, bf[nt].z, bf[nt].w);
        }
    };

    stage(0, 0); stage(1, 1); stage(2, 2);
#pragma unroll
    for (int c = 0; c < 12; ++c) {
        if (c <= 8) { stage(c + 3, (c + 3) & 3); CP_WAIT(3); }
        else if (c == 9)  { CP_WAIT(2); }
        else if (c == 10) { CP_WAIT(1); }
        else              { CP_WAIT(0); }
        __syncwarp();
        consume(c, c & 3);
    }

    // ---------------- H (fp32 C-frags) -> G23 tf32 A-frags via shfl ----------------
    uint32_t Afr[4][4];
    {
        const int srcA = (ln & 0x1C) | ((ln & 3) >> 1);
        const int srcB = srcA + 2;
        const bool hi = (ln & 1);
#pragma unroll
        for (int q = 0; q < 4; ++q) {
            const float e0 = __shfl_sync(0xFFFFFFFFu, acc1[q][0], srcA);
            const float e1 = __shfl_sync(0xFFFFFFFFu, acc1[q][1], srcA);
            const float e2 = __shfl_sync(0xFFFFFFFFu, acc1[q][2], srcA);
            const float e3 = __shfl_sync(0xFFFFFFFFu, acc1[q][3], srcA);
            const float f0 = __shfl_sync(0xFFFFFFFFu, acc1[q][0], srcB);
            const float f1 = __shfl_sync(0xFFFFFFFFu, acc1[q][1], srcB);
            const float f2 = __shfl_sync(0xFFFFFFFFu, acc1[q][2], srcB);
            const float f3 = __shfl_sync(0xFFFFFFFFu, acc1[q][3], srcB);
            Afr[q][0] = f2tf32(hi ? e1 : e0);
            Afr[q][1] = f2tf32(hi ? e3 : e2);
            Afr[q][2] = f2tf32(hi ? f1 : f0);
            Afr[q][3] = f2tf32(hi ? f3 : f2);
        }
    }

    // ---------------- epilogue row-offset table (once, in smem) --------------------
    if (ln < 16) {
        const int R = r0 + wr0 + ln;
        const int b = R / 196;
        const int p = R - b * 196;
        sts64i(wbuf + OFFB + (ln << 3), (b * 197 + p + 1) * 768, (p + 1) * 768);
    }
    __syncwarp();

    // ---------------- G23: 6 groups of 16 n-tiles (128 cols), smem-staged epilogue --
    const uint32_t rbuf = wbuf;                       // result tile: 16 rows x 132 floats
    const uint32_t stsA = rbuf + (uint32_t)gr * RSE + (uint32_t)(q2 << 2);
    const uint32_t stsB = stsA + 8 * RSE;

    for (int gidx = 0; gidx < 6; ++gidx) {
        // software-pipelined weight loads: prefetch tile tt+1 during mma of tt
        uint4 p0 = __ldg(&g_W23F[((gidx * 16) << 1) * 32 + ln]);
        uint4 p1 = __ldg(&g_W23F[(((gidx * 16) << 1) + 1) * 32 + ln]);
#pragma unroll
        for (int tt = 0; tt < 16; ++tt) {
            uint4 n0, n1;
            if (tt < 15) {
                const int nn = gidx * 16 + tt + 1;
                n0 = __ldg(&g_W23F[((nn << 1) + 0) * 32 + ln]);
                n1 = __ldg(&g_W23F[((nn << 1) + 1) * 32 + ln]);
            }
            float c[4] = {0.f, 0.f, 0.f, 0.f};
            mma_tf32(c, Afr[0], p0.x, p0.y);
            mma_tf32(c, Afr[1], p0.z, p0.w);
            mma_tf32(c, Afr[2], p1.x, p1.y);
            mma_tf32(c, Afr[3], p1.z, p1.w);

            const uint32_t coff = (uint32_t)(tt << 5);       // tt*8 floats
            sts64(stsA + coff, c[0], c[1]);
            sts64(stsB + coff, c[2], c[3]);
            p0 = n0; p1 = n1;
        }
        __syncwarp();

        // coalesced write-out: one full row (128 cols) per instruction
        const int gcol = gidx * 128 + (ln << 2);
        const float4 be = __ldg((const float4*)(g_beff + gcol));
        const uint32_t rdbase = rbuf + (uint32_t)(ln << 4);
#pragma unroll
        for (int lr = 0; lr < 16; ++lr) {
            const int2 off = lds64i(wbuf + OFFB + (lr << 3));   // broadcast
            const float4 rv = lds128(rdbase + (uint32_t)lr * RSE);
            const float4 pv = __ldg((const float4*)(pos + off.y + gcol));
            float4 o;
            o.x = rv.x + pv.x + be.x;
            o.y = rv.y + pv.y + be.y;
            o.z = rv.z + pv.z + be.z;
            o.w = rv.w + pv.w + be.w;
            *(float4*)(out + off.x + gcol) = o;
        }
        __syncwarp();   // protect tile before next group's STS
    }
}

extern "C" void kernel_launch(void* const* d_in, const int* in_sizes, int n_in,
                              void* d_out, int out_size)
{
    const float* X   = (const float*)d_in[0];
    const float* W1  = (const float*)d_in[1];
    const float* b1  = (const float*)d_in[2];
    const float* W2  = (const float*)d_in[3];
    const float* b2  = (const float*)d_in[4];
    const float* W3  = (const float*)d_in[5];
    const float* b3  = (const float*)d_in[6];
    const float* cls = (const float*)d_in[7];
    const float* pos = (const float*)d_in[8];
    float* out = (float*)d_out;

    const int smem = 4 * WSLOT;   // 69632 B
    cudaFuncSetAttribute(patch_embed_mma,
                         cudaFuncAttributeMaxDynamicSharedMemorySize, smem);

    prep_kernel<<<192, 128>>>(W1, b1, W2, b2, W3, b3, cls, pos, out);
    patch_embed_mma<<<392, THREADS, smem>>>(X, pos, out);
}

// round 13
// speedup vs baseline: 1.0747x; 1.0747x over previous
#include <cuda_runtime.h>
#include <cuda_bf16.h>
#include <cstdint>

// PatchEmbeder via mma.sync tf32 m16n8k8 + affine collapse.
// out[b,0,:]   = cls + pos[0]                                  (prep kernel)
// out[b,p+1,:] = x_patch @ W1 @ (W2@W3) + beff + pos[p+1]      (main kernel)
// x[b,p,k] = inputs[b, k/256, p, (k%256)/16, k%16]
// B=128, P=196 -> 25088 rows = 392 CTAs x 64 rows. K1=768, N1=32(=K2), E=768.
//
// R13: (1) prep back to 96x256 (R12's 192x128 doubled redundant per-block work);
// (2) G23 restructure: H exchanged through smem, each warp holds A-frags for all
// 64 rows and does 24/96 n-tiles -> W23F fragment traffic per warp /4 (attacks
// the persistent L1 ~55% bottleneck).

#define THREADS 128
#define RS2     272              // G1 staging row stride bytes (68 words, ==4 mod 32)
#define BUF2    (16 * RS2)       // 4352 B per ring buffer
#define WSLOT   (4 * BUF2)       // 17408 B per warp (G1 ring)
#define RSE     528              // G23 result tile row stride bytes (132 words)
#define HS      144              // H exchange row stride bytes (36 words)
#define HOFF    33792            // H buffer offset (after 64*528 result tile)
#define OFFO    43008            // row-offset table (after H buffer 64*144)

// ---- device scratch (rebuilt every replay by prep_kernel) ----
__device__ __align__(16) uint4 g_W1F [48 * 4 * 32];   // [kt16 48][nt 4][lane]
__device__ __align__(16) uint4 g_W23F[96 * 2 * 32];   // [nt 96][kt8-pair 2][lane]
__device__ __align__(16) float g_beff[768];

__device__ __forceinline__ uint32_t f2tf32(float f) {
    uint32_t r;
    asm("cvt.rna.tf32.f32 %0, %1;" : "=r"(r) : "f"(f));
    return r;
}
__device__ __forceinline__ void mma_tf32(float* c, const uint32_t a[4],
                                         uint32_t b0, uint32_t b1) {
    asm("mma.sync.aligned.m16n8k8.row.col.f32.tf32.tf32.f32 "
        "{%0,%1,%2,%3}, {%4,%5,%6,%7}, {%8,%9}, {%0,%1,%2,%3};"
        : "+f"(c[0]), "+f"(c[1]), "+f"(c[2]), "+f"(c[3])
        : "r"(a[0]), "r"(a[1]), "r"(a[2]), "r"(a[3]), "r"(b0), "r"(b1));
}
__device__ __forceinline__ uint32_t smem_u32(const void* p) {
    uint32_t a;
    asm("{ .reg .u64 t; cvta.to.shared.u64 t, %1; cvt.u32.u64 %0, t; }" : "=r"(a) : "l"(p));
    return a;
}
__device__ __forceinline__ void cp_async16(uint32_t dst, const void* src) {
    asm volatile("cp.async.cg.shared.global [%0], [%1], 16;" :: "r"(dst), "l"(src));
}
#define CP_COMMIT()  asm volatile("cp.async.commit_group;" ::: "memory")
#define CP_WAIT(N)   asm volatile("cp.async.wait_group %0;" :: "n"(N) : "memory")
__device__ __forceinline__ float lds32(uint32_t a) {
    float v;
    asm volatile("ld.shared.f32 %0, [%1];" : "=f"(v) : "r"(a));
    return v;
}
__device__ __forceinline__ void sts64(uint32_t a, float x, float y) {
    asm volatile("st.shared.v2.f32 [%0], {%1,%2};" :: "r"(a), "f"(x), "f"(y));
}
__device__ __forceinline__ void sts64i(uint32_t a, int x, int y) {
    asm volatile("st.shared.v2.u32 [%0], {%1,%2};" :: "r"(a), "r"(x), "r"(y));
}
__device__ __forceinline__ int2 lds64i(uint32_t a) {
    int2 v;
    asm volatile("ld.shared.v2.u32 {%0,%1}, [%2];" : "=r"(v.x), "=r"(v.y) : "r"(a));
    return v;
}
__device__ __forceinline__ float4 lds128(uint32_t a) {
    float4 v;
    asm volatile("ld.shared.v4.f32 {%0,%1,%2,%3}, [%4];"
                 : "=f"(v.x), "=f"(v.y), "=f"(v.z), "=f"(v.w) : "r"(a));
    return v;
}

// =====================================================================
// prep: bake W1 / W23=W2@W3 tf32 fragments, beff, cls rows.
// grid 96 x 256 = 24576 threads (R10 shape; coalesced W23 e-mapping kept).
// =====================================================================
__global__ void prep_kernel(const float* __restrict__ W1, const float* __restrict__ b1,
                            const float* __restrict__ W2, const float* __restrict__ b2,
                            const float* __restrict__ W3, const float* __restrict__ b3,
                            const float* __restrict__ cls, const float* __restrict__ pos,
                            float* __restrict__ out)
{
    __shared__ float W2s[32 * 65];   // padded stride 65
    __shared__ float t1s[64];

    const int t = threadIdx.x;
    const int g = blockIdx.x * 256 + t;   // 0..24575

#pragma unroll
    for (int i = t; i < 2048; i += 256)
        W2s[(i >> 6) * 65 + (i & 63)] = __ldg(W2 + i);
    __syncthreads();

    if (t < 64) {
        float acc = __ldg(b2 + t);
#pragma unroll
        for (int i = 0; i < 32; ++i) acc += __ldg(b1 + i) * W2s[i * 65 + t];
        t1s[t] = acc;
    }
    __syncthreads();

    // ---- W1 fragment element (k = g>>5 in 0..767, n = g&31) ----
    {
        const int k = g >> 5, n = g & 31;
        const uint32_t tv = f2tf32(__ldg(W1 + k * 32 + n));
        const int kt16 = k >> 4;
        const int comp = (((k >> 3) & 1) << 1) | ((k & 7) >> 2);
        const int lane = ((n & 7) << 2) | (k & 3);
        const int nt = n >> 3;
        ((uint32_t*)&g_W1F[(kt16 * 4 + nt) * 32 + lane])[comp] = tv;
    }
    // ---- W23 fragment + beff: lanes span e -> W3 reads coalesced ----
    {
        const int e = g % 768, k2 = g / 768;
        float acc = 0.f;
        float accb = (k2 == 0) ? __ldg(b3 + e) : 0.f;
#pragma unroll
        for (int j = 0; j < 64; ++j) {
            const float w3v = __ldg(W3 + j * 768 + e);   // coalesced across lanes
            acc += W2s[k2 * 65 + j] * w3v;               // warp-uniform broadcast
            if (k2 == 0) accb += t1s[j] * w3v;
        }
        const uint32_t tv = f2tf32(acc);
        const int nt = e >> 3, pair = k2 >> 4;
        const int comp = (((k2 >> 3) & 1) << 1) | ((k2 & 7) >> 2);
        const int lane = ((e & 7) << 2) | (k2 & 3);
        ((uint32_t*)&g_W23F[(nt * 2 + pair) * 32 + lane])[comp] = tv;
        if (k2 == 0) g_beff[e] = accb;
    }
    // ---- cls rows ----
    {
        const int e4 = g % 192, b = g / 192;
        const float4 c = __ldg((const float4*)cls + e4);
        const float4 pp = __ldg((const float4*)pos + e4);
        *((float4*)(out + (size_t)b * 197 * 768) + e4) =
            make_float4(c.x + pp.x, c.y + pp.y, c.z + pp.z, c.w + pp.w);
    }
}

// =====================================================================
// main: 392 CTAs x 128 threads (4 warps), 64 rows.
// G1: warp-private depth-4 cp.async ring (as R12).
// G23: H exchanged via smem; each warp holds A-frags for ALL 64 rows and
// handles 4 n-tiles per 128-col group (B-fragment traffic /4).
// =====================================================================
__global__ __launch_bounds__(THREADS, 3)
void patch_embed_mma(const float* __restrict__ X, const float* __restrict__ pos,
                     float* __restrict__ out)
{
    extern __shared__ char smem[];
    const uint32_t sb = smem_u32(smem);
    const int t = threadIdx.x;
    const int w = t >> 5;
    const int ln = t & 31;
    const int r0 = blockIdx.x * 64;
    const int wr0 = w << 4;                       // warp's 16 rows (G1 / write-out)
    const uint32_t wbuf = sb + (uint32_t)w * WSLOT;

    const int gr = ln >> 2;                       // fragment row 0..7
    const int q2 = (ln & 3) << 1;                 // C-fragment col pair base

    // per-row gmem bases for this warp's 16 G1 rows
    const float* rowbase[16];
#pragma unroll
    for (int lr = 0; lr < 16; ++lr) {
        const int R = r0 + wr0 + lr;
        const int b = R / 196;
        const int p = R - b * 196;
        rowbase[lr] = X + (((size_t)b * 3 * 196 + p) << 8);
    }

    // ---------------- G1: H[16x32] = Xrows @ W1, tf32, depth-4 ring ----------------
    float acc1[4][4];
#pragma unroll
    for (int i = 0; i < 4; ++i)
#pragma unroll
        for (int j = 0; j < 4; ++j) acc1[i][j] = 0.f;

    auto stage = [&](int kc, int d) {
        const size_t choff = (size_t)(kc >> 2) * (196 << 8) + ((kc & 3) << 6) + ((ln & 15) << 2);
        const uint32_t dst = wbuf + (uint32_t)d * BUF2 + (uint32_t)((ln & 15) << 4);
        const int lr0 = ln >> 4;
#pragma unroll
        for (int it = 0; it < 8; ++it) {
            const int lr = (it << 1) + lr0;
            cp_async16(dst + (uint32_t)lr * RS2, rowbase[lr] + choff);
        }
        CP_COMMIT();
    };

    auto consume = [&](int kc, int d) {
        const uint32_t a0 = wbuf + (uint32_t)d * BUF2 + (uint32_t)gr * RS2
                          + (uint32_t)((ln & 3) << 2);
#pragma unroll
        for (int gq = 0; gq < 4; ++gq) {            // 4 kt16-groups per 64-col chunk
            const uint32_t ae = a0 + (uint32_t)(gq << 6);
            uint32_t Ae[4], Ao[4];
            Ae[0] = f2tf32(lds32(ae));
            Ae[1] = f2tf32(lds32(ae + 8 * RS2));
            Ae[2] = f2tf32(lds32(ae + 16));
            Ae[3] = f2tf32(lds32(ae + 8 * RS2 + 16));
            Ao[0] = f2tf32(lds32(ae + 32));
            Ao[1] = f2tf32(lds32(ae + 8 * RS2 + 32));
            Ao[2] = f2tf32(lds32(ae + 48));
            Ao[3] = f2tf32(lds32(ae + 8 * RS2 + 48));

            const uint4* bp = &g_W1F[(((kc << 2) + gq) << 2) * 32 + ln];
            uint4 bf[4];
#pragma unroll
            for (int nt = 0; nt < 4; ++nt) bf[nt] = __ldg(bp + nt * 32);
#pragma unroll
            for (int nt = 0; nt < 4; ++nt) mma_tf32(acc1[nt], Ae, bf[nt].x, bf[nt].y);
#pragma unroll
            for (int nt = 0; nt < 4; ++nt) mma_tf32(acc1[nt], Ao, bf[nt].z, bf[nt].w);
        }
    };

    stage(0, 0); stage(1, 1); stage(2, 2);
#pragma unroll
    for (int c = 0; c < 12; ++c) {
        if (c <= 8) { stage(c + 3, (c + 3) & 3); CP_WAIT(3); }
        else if (c == 9)  { CP_WAIT(2); }
        else if (c == 10) { CP_WAIT(1); }
        else              { CP_WAIT(0); }
        __syncwarp();
        consume(c, c & 3);
    }

    // ---------------- exchange H through smem (all rings dead after this sync) -----
    __syncthreads();
    {
        const uint32_t hb = sb + HOFF + (uint32_t)(wr0 + gr) * HS + (uint32_t)(q2 << 2);
#pragma unroll
        for (int nt = 0; nt < 4; ++nt) {
            sts64(hb + (uint32_t)(nt << 5),          acc1[nt][0], acc1[nt][1]);
            sts64(hb + (uint32_t)(nt << 5) + 8 * HS, acc1[nt][2], acc1[nt][3]);
        }
    }
    // row-offset table for all 64 rows (out offset, pos offset)
    if (t < 64) {
        const int R = r0 + t;
        const int b = R / 196;
        const int p = R - b * 196;
        sts64i(sb + OFFO + (t << 3), (b * 197 + p + 1) * 768, (p + 1) * 768);
    }
    __syncthreads();

    // ---------------- A-fragments for ALL 64 rows (tf32, from smem H) --------------
    uint32_t Afr[4][4][4];   // [row-block][kq][reg]
    {
        const uint32_t hb = sb + HOFF + (uint32_t)((ln & 3) << 2);
#pragma unroll
        for (int rb = 0; rb < 4; ++rb) {
            const uint32_t base = hb + (uint32_t)(rb * 16 + gr) * HS;
#pragma unroll
            for (int q = 0; q < 4; ++q) {
                Afr[rb][q][0] = f2tf32(lds32(base + (q << 5)));
                Afr[rb][q][1] = f2tf32(lds32(base + (q << 5) + 8 * HS));
                Afr[rb][q][2] = f2tf32(lds32(base + (q << 5) + 16));
                Afr[rb][q][3] = f2tf32(lds32(base + (q << 5) + 16 + 8 * HS));
            }
        }
    }

    // ---------------- G23: 6 groups x (4 tiles/warp over all 64 rows) --------------
    const uint32_t res = sb;                      // result tile: 64 rows x 132 floats

    for (int gidx = 0; gidx < 6; ++gidx) {
        const int nt0 = gidx * 16 + w * 4;        // this warp's 4 tiles in the group
        uint4 p0 = __ldg(&g_W23F[((nt0 << 1) + 0) * 32 + ln]);
        uint4 p1 = __ldg(&g_W23F[((nt0 << 1) + 1) * 32 + ln]);
#pragma unroll
        for (int i = 0; i < 4; ++i) {
            uint4 n0, n1;
            if (i < 3) {
                n0 = __ldg(&g_W23F[(((nt0 + i + 1) << 1) + 0) * 32 + ln]);
                n1 = __ldg(&g_W23F[(((nt0 + i + 1) << 1) + 1) * 32 + ln]);
            }
            float c[4][4];
#pragma unroll
            for (int rb = 0; rb < 4; ++rb) {
                c[rb][0] = 0.f; c[rb][1] = 0.f; c[rb][2] = 0.f; c[rb][3] = 0.f;
            }
#pragma unroll
            for (int rb = 0; rb < 4; ++rb) {
                mma_tf32(c[rb], Afr[rb][0], p0.x, p0.y);
                mma_tf32(c[rb], Afr[rb][1], p0.z, p0.w);
                mma_tf32(c[rb], Afr[rb][2], p1.x, p1.y);
                mma_tf32(c[rb], Afr[rb][3], p1.z, p1.w);
            }
            // store to result tile: cols ((w*4+i)*8 + q2) of the 128-col group
            const uint32_t cb = res + (uint32_t)(((w << 2) + i) << 5) + (uint32_t)(q2 << 2);
#pragma unroll
            for (int rb = 0; rb < 4; ++rb) {
                const uint32_t ra = cb + (uint32_t)(rb * 16 + gr) * RSE;
                sts64(ra,           c[rb][0], c[rb][1]);
                sts64(ra + 8 * RSE, c[rb][2], c[rb][3]);
            }
            p0 = n0; p1 = n1;
        }
        __syncthreads();

        // cooperative coalesced write-out: warp w writes rows [w*16, w*16+16)
        const int gcol = gidx * 128 + (ln << 2);
        const float4 be = __ldg((const float4*)(g_beff + gcol));
#pragma unroll
        for (int lr = 0; lr < 16; ++lr) {
            const int row = wr0 + lr;
            const int2 off = lds64i(sb + OFFO + (row << 3));   // broadcast
            const float4 rv = lds128(res + (uint32_t)row * RSE + (uint32_t)(ln << 4));
            const float4 pv = __ldg((const float4*)(pos + off.y + gcol));
            float4 o;
            o.x = rv.x + pv.x + be.x;
            o.y = rv.y + pv.y + be.y;
            o.z = rv.z + pv.z + be.z;
            o.w = rv.w + pv.w + be.w;
            *(float4*)(out + off.x + gcol) = o;
        }
        __syncthreads();   // protect tile before next group's STS
    }
}

extern "C" void kernel_launch(void* const* d_in, const int* in_sizes, int n_in,
                              void* d_out, int out_size)
{
    const float* X   = (const float*)d_in[0];
    const float* W1  = (const float*)d_in[1];
    const float* b1  = (const float*)d_in[2];
    const float* W2  = (const float*)d_in[3];
    const float* b2  = (const float*)d_in[4];
    const float* W3  = (const float*)d_in[5];
    const float* b3  = (const float*)d_in[6];
    const float* cls = (const float*)d_in[7];
    const float* pos = (const float*)d_in[8];
    float* out = (float*)d_out;

    const int smem = 4 * WSLOT;   // 69632 B (G1 ring; aliased by G23 tiles)
    cudaFuncSetAttribute(patch_embed_mma,
                         cudaFuncAttributeMaxDynamicSharedMemorySize, smem);

    prep_kernel<<<96, 256>>>(W1, b1, W2, b2, W3, b3, cls, pos, out);
    patch_embed_mma<<<392, THREADS, smem>>>(X, pos, out);
}

// round 14
// speedup vs baseline: 1.0867x; 1.0112x over previous
#include <cuda_runtime.h>
#include <cuda_bf16.h>
#include <cstdint>

// PatchEmbeder via mma.sync tf32 m16n8k8 + affine collapse.
// out[b,0,:]   = cls + pos[0]                                  (prep kernel)
// out[b,p+1,:] = x_patch @ W1 @ (W2@W3) + beff + pos[p+1]      (main kernel)
// x[b,p,k] = inputs[b, k/256, p, (k%256)/16, k%16]
// B=128, P=196 -> 25088 rows = 392 CTAs x 64 rows. K1=768, N1=32(=K2), E=768.
//
// R14: smem diet to grow the L1D carveout (228KB - smem). Ring depth 2, G23
// 64-col groups -> 35.3KB/CTA (was 69.6). 3 CTAs/SM = 106KB smem => ~122KB L1D:
// W1F (98KB, read per-warp in G1) and W23F (49KB) become L1-resident instead of
// paying 234-cyc L2 on every fragment load.

#define THREADS 128
#define RS2     272              // staging/result row stride bytes (68 words, ==4 mod 32)
#define BUF2    (16 * RS2)       // 4352 B per ring buffer
#define WSLOT   (2 * BUF2)       // 8704 B per warp (depth-2 ring)
#define HS      144              // H exchange row stride bytes (36 words)
#define HOFF    17408            // H buffer offset (after 64*272 result tile)
#define OFFO    34816            // row-offset table (dedicated, after rings)
#define SMEMSZ  35328

// ---- device scratch (rebuilt every replay by prep_kernel) ----
__device__ __align__(16) uint4 g_W1F [48 * 4 * 32];   // [kt16 48][nt 4][lane]
__device__ __align__(16) uint4 g_W23F[96 * 2 * 32];   // [nt 96][kt8-pair 2][lane]
__device__ __align__(16) float g_beff[768];

__device__ __forceinline__ uint32_t f2tf32(float f) {
    uint32_t r;
    asm("cvt.rna.tf32.f32 %0, %1;" : "=r"(r) : "f"(f));
    return r;
}
__device__ __forceinline__ void mma_tf32(float* c, const uint32_t a[4],
                                         uint32_t b0, uint32_t b1) {
    asm("mma.sync.aligned.m16n8k8.row.col.f32.tf32.tf32.f32 "
        "{%0,%1,%2,%3}, {%4,%5,%6,%7}, {%8,%9}, {%0,%1,%2,%3};"
        : "+f"(c[0]), "+f"(c[1]), "+f"(c[2]), "+f"(c[3])
        : "r"(a[0]), "r"(a[1]), "r"(a[2]), "r"(a[3]), "r"(b0), "r"(b1));
}
__device__ __forceinline__ uint32_t smem_u32(const void* p) {
    uint32_t a;
    asm("{ .reg .u64 t; cvta.to.shared.u64 t, %1; cvt.u32.u64 %0, t; }" : "=r"(a) : "l"(p));
    return a;
}
__device__ __forceinline__ void cp_async16(uint32_t dst, const void* src) {
    asm volatile("cp.async.cg.shared.global [%0], [%1], 16;" :: "r"(dst), "l"(src));
}
#define CP_COMMIT()  asm volatile("cp.async.commit_group;" ::: "memory")
#define CP_WAIT(N)   asm volatile("cp.async.wait_group %0;" :: "n"(N) : "memory")
__device__ __forceinline__ float lds32(uint32_t a) {
    float v;
    asm volatile("ld.shared.f32 %0, [%1];" : "=f"(v) : "r"(a));
    return v;
}
__device__ __forceinline__ void sts64(uint32_t a, float x, float y) {
    asm volatile("st.shared.v2.f32 [%0], {%1,%2};" :: "r"(a), "f"(x), "f"(y));
}
__device__ __forceinline__ void sts64i(uint32_t a, int x, int y) {
    asm volatile("st.shared.v2.u32 [%0], {%1,%2};" :: "r"(a), "r"(x), "r"(y));
}
__device__ __forceinline__ int2 lds64i(uint32_t a) {
    int2 v;
    asm volatile("ld.shared.v2.u32 {%0,%1}, [%2];" : "=r"(v.x), "=r"(v.y) : "r"(a));
    return v;
}
__device__ __forceinline__ float4 lds128(uint32_t a) {
    float4 v;
    asm volatile("ld.shared.v4.f32 {%0,%1,%2,%3}, [%4];"
                 : "=f"(v.x), "=f"(v.y), "=f"(v.z), "=f"(v.w) : "r"(a));
    return v;
}

// =====================================================================
// prep: bake W1 / W23=W2@W3 tf32 fragments, beff, cls rows.
// grid 96 x 256 = 24576 threads.
// =====================================================================
__global__ void prep_kernel(const float* __restrict__ W1, const float* __restrict__ b1,
                            const float* __restrict__ W2, const float* __restrict__ b2,
                            const float* __restrict__ W3, const float* __restrict__ b3,
                            const float* __restrict__ cls, const float* __restrict__ pos,
                            float* __restrict__ out)
{
    __shared__ float W2s[32 * 65];   // padded stride 65
    __shared__ float t1s[64];

    const int t = threadIdx.x;
    const int g = blockIdx.x * 256 + t;   // 0..24575

#pragma unroll
    for (int i = t; i < 2048; i += 256)
        W2s[(i >> 6) * 65 + (i & 63)] = __ldg(W2 + i);
    __syncthreads();

    if (t < 64) {
        float acc = __ldg(b2 + t);
#pragma unroll
        for (int i = 0; i < 32; ++i) acc += __ldg(b1 + i) * W2s[i * 65 + t];
        t1s[t] = acc;
    }
    __syncthreads();

    // ---- W1 fragment element (k = g>>5 in 0..767, n = g&31) ----
    {
        const int k = g >> 5, n = g & 31;
        const uint32_t tv = f2tf32(__ldg(W1 + k * 32 + n));
        const int kt16 = k >> 4;
        const int comp = (((k >> 3) & 1) << 1) | ((k & 7) >> 2);
        const int lane = ((n & 7) << 2) | (k & 3);
        const int nt = n >> 3;
        ((uint32_t*)&g_W1F[(kt16 * 4 + nt) * 32 + lane])[comp] = tv;
    }
    // ---- W23 fragment + beff: lanes span e -> W3 reads coalesced ----
    {
        const int e = g % 768, k2 = g / 768;
        float acc = 0.f;
        float accb = (k2 == 0) ? __ldg(b3 + e) : 0.f;
#pragma unroll
        for (int j = 0; j < 64; ++j) {
            const float w3v = __ldg(W3 + j * 768 + e);   // coalesced across lanes
            acc += W2s[k2 * 65 + j] * w3v;               // warp-uniform broadcast
            if (k2 == 0) accb += t1s[j] * w3v;
        }
        const uint32_t tv = f2tf32(acc);
        const int nt = e >> 3, pair = k2 >> 4;
        const int comp = (((k2 >> 3) & 1) << 1) | ((k2 & 7) >> 2);
        const int lane = ((e & 7) << 2) | (k2 & 3);
        ((uint32_t*)&g_W23F[(nt * 2 + pair) * 32 + lane])[comp] = tv;
        if (k2 == 0) g_beff[e] = accb;
    }
    // ---- cls rows ----
    {
        const int e4 = g % 192, b = g / 192;
        const float4 c = __ldg((const float4*)cls + e4);
        const float4 pp = __ldg((const float4*)pos + e4);
        *((float4*)(out + (size_t)b * 197 * 768) + e4) =
            make_float4(c.x + pp.x, c.y + pp.y, c.z + pp.z, c.w + pp.w);
    }
}

// =====================================================================
// main: 392 CTAs x 128 threads (4 warps), 64 rows.
// G1: warp-private depth-2 cp.async ring of 64-col fp32 X chunks.
// G23: H exchanged via smem; each warp holds A-frags for ALL 64 rows;
// 12 groups of 64 cols, 2 n-tiles per warp per group.
// =====================================================================
__global__ __launch_bounds__(THREADS, 3)
void patch_embed_mma(const float* __restrict__ X, const float* __restrict__ pos,
                     float* __restrict__ out)
{
    extern __shared__ char smem[];
    const uint32_t sb = smem_u32(smem);
    const int t = threadIdx.x;
    const int w = t >> 5;
    const int ln = t & 31;
    const int r0 = blockIdx.x * 64;
    const int wr0 = w << 4;                       // warp's 16 rows (G1 / write-out)
    const uint32_t wbuf = sb + (uint32_t)w * WSLOT;

    const int gr = ln >> 2;                       // fragment row 0..7
    const int q2 = (ln & 3) << 1;                 // C-fragment col pair base

    // per-row gmem bases for this warp's 16 G1 rows
    const float* rowbase[16];
#pragma unroll
    for (int lr = 0; lr < 16; ++lr) {
        const int R = r0 + wr0 + lr;
        const int b = R / 196;
        const int p = R - b * 196;
        rowbase[lr] = X + (((size_t)b * 3 * 196 + p) << 8);
    }

    // ---------------- G1: H[16x32] = Xrows @ W1, tf32, depth-2 ring ----------------
    float acc1[4][4];
#pragma unroll
    for (int i = 0; i < 4; ++i)
#pragma unroll
        for (int j = 0; j < 4; ++j) acc1[i][j] = 0.f;

    // stage 64-col chunk kc (0..11) into ring slot d
    auto stage = [&](int kc, int d) {
        const size_t choff = (size_t)(kc >> 2) * (196 << 8) + ((kc & 3) << 6) + ((ln & 15) << 2);
        const uint32_t dst = wbuf + (uint32_t)d * BUF2 + (uint32_t)((ln & 15) << 4);
        const int lr0 = ln >> 4;
#pragma unroll
        for (int it = 0; it < 8; ++it) {
            const int lr = (it << 1) + lr0;
            cp_async16(dst + (uint32_t)lr * RS2, rowbase[lr] + choff);
        }
        CP_COMMIT();
    };

    auto consume = [&](int kc, int d) {
        const uint32_t a0 = wbuf + (uint32_t)d * BUF2 + (uint32_t)gr * RS2
                          + (uint32_t)((ln & 3) << 2);
#pragma unroll
        for (int gq = 0; gq < 4; ++gq) {            // 4 kt16-groups per 64-col chunk
            const uint32_t ae = a0 + (uint32_t)(gq << 6);
            uint32_t Ae[4], Ao[4];
            Ae[0] = f2tf32(lds32(ae));
            Ae[1] = f2tf32(lds32(ae + 8 * RS2));
            Ae[2] = f2tf32(lds32(ae + 16));
            Ae[3] = f2tf32(lds32(ae + 8 * RS2 + 16));
            Ao[0] = f2tf32(lds32(ae + 32));
            Ao[1] = f2tf32(lds32(ae + 8 * RS2 + 32));
            Ao[2] = f2tf32(lds32(ae + 48));
            Ao[3] = f2tf32(lds32(ae + 8 * RS2 + 48));

            const uint4* bp = &g_W1F[(((kc << 2) + gq) << 2) * 32 + ln];
            uint4 bf[4];
#pragma unroll
            for (int nt = 0; nt < 4; ++nt) bf[nt] = __ldg(bp + nt * 32);
#pragma unroll
            for (int nt = 0; nt < 4; ++nt) mma_tf32(acc1[nt], Ae, bf[nt].x, bf[nt].y);
#pragma unroll
            for (int nt = 0; nt < 4; ++nt) mma_tf32(acc1[nt], Ao, bf[nt].z, bf[nt].w);
        }
    };

    stage(0, 0);
#pragma unroll
    for (int c = 0; c < 12; ++c) {
        if (c < 11) { stage(c + 1, (c + 1) & 1); CP_WAIT(1); }
        else        { CP_WAIT(0); }
        __syncwarp();
        consume(c, c & 1);
    }

    // ---------------- exchange H through smem (rings dead after this sync) ---------
    __syncthreads();
    {
        const uint32_t hb = sb + HOFF + (uint32_t)(wr0 + gr) * HS + (uint32_t)(q2 << 2);
#pragma unroll
        for (int nt = 0; nt < 4; ++nt) {
            sts64(hb + (uint32_t)(nt << 5),          acc1[nt][0], acc1[nt][1]);
            sts64(hb + (uint32_t)(nt << 5) + 8 * HS, acc1[nt][2], acc1[nt][3]);
        }
    }
    // row-offset table for all 64 rows (out offset, pos offset) — dedicated region
    if (t < 64) {
        const int R = r0 + t;
        const int b = R / 196;
        const int p = R - b * 196;
        sts64i(sb + OFFO + (t << 3), (b * 197 + p + 1) * 768, (p + 1) * 768);
    }
    __syncthreads();

    // ---------------- A-fragments for ALL 64 rows (tf32, from smem H) --------------
    uint32_t Afr[4][4][4];   // [row-block][kq][reg]
    {
        const uint32_t hb = sb + HOFF + (uint32_t)((ln & 3) << 2);
#pragma unroll
        for (int rb = 0; rb < 4; ++rb) {
            const uint32_t base = hb + (uint32_t)(rb * 16 + gr) * HS;
#pragma unroll
            for (int q = 0; q < 4; ++q) {
                Afr[rb][q][0] = f2tf32(lds32(base + (q << 5)));
                Afr[rb][q][1] = f2tf32(lds32(base + (q << 5) + 8 * HS));
                Afr[rb][q][2] = f2tf32(lds32(base + (q << 5) + 16));
                Afr[rb][q][3] = f2tf32(lds32(base + (q << 5) + 16 + 8 * HS));
            }
        }
    }

    // ---------------- G23: 12 groups of 64 cols; 2 n-tiles/warp/group --------------
    const uint32_t res = sb;                      // result tile: 64 rows x 68 floats
    const int colw = ln & 15;                     // epilogue: lane's float4 column
    const int rowsel = ln >> 4;                   // epilogue: row within pair

    for (int gidx = 0; gidx < 12; ++gidx) {
        const int nt0 = gidx * 8 + w * 2;         // this warp's 2 tiles in the group
        uint4 p0 = __ldg(&g_W23F[((nt0 << 1) + 0) * 32 + ln]);
        uint4 p1 = __ldg(&g_W23F[((nt0 << 1) + 1) * 32 + ln]);
#pragma unroll
        for (int i = 0; i < 2; ++i) {
            uint4 n0, n1;
            if (i == 0) {
                n0 = __ldg(&g_W23F[(((nt0 + 1) << 1) + 0) * 32 + ln]);
                n1 = __ldg(&g_W23F[(((nt0 + 1) << 1) + 1) * 32 + ln]);
            }
            float c[4][4];
#pragma unroll
            for (int rb = 0; rb < 4; ++rb) {
                c[rb][0] = 0.f; c[rb][1] = 0.f; c[rb][2] = 0.f; c[rb][3] = 0.f;
            }
#pragma unroll
            for (int rb = 0; rb < 4; ++rb) {
                mma_tf32(c[rb], Afr[rb][0], p0.x, p0.y);
                mma_tf32(c[rb], Afr[rb][1], p0.z, p0.w);
                mma_tf32(c[rb], Afr[rb][2], p1.x, p1.y);
                mma_tf32(c[rb], Afr[rb][3], p1.z, p1.w);
            }
            // store: cols ((w*2+i)*8 + q2) of the 64-col group
            const uint32_t cb = res + (uint32_t)(((w << 1) + i) << 5) + (uint32_t)(q2 << 2);
#pragma unroll
            for (int rb = 0; rb < 4; ++rb) {
                const uint32_t ra = cb + (uint32_t)(rb * 16 + gr) * RS2;
                sts64(ra,           c[rb][0], c[rb][1]);
                sts64(ra + 8 * RS2, c[rb][2], c[rb][3]);
            }
            p0 = n0; p1 = n1;
        }
        __syncthreads();

        // cooperative write-out: warp w writes rows [w*16, w*16+16), 2 rows/iter
        const int gcol = gidx * 64;
        const float4 be = __ldg((const float4*)(g_beff + gcol) + colw);
#pragma unroll
        for (int it = 0; it < 8; ++it) {
            const int row = wr0 + (it << 1) + rowsel;
            const int2 off = lds64i(sb + OFFO + (row << 3));
            const float4 rv = lds128(res + (uint32_t)row * RS2 + (uint32_t)(colw << 4));
            const float4 pv = __ldg((const float4*)(pos + off.y + gcol) + colw);
            float4 o;
            o.x = rv.x + pv.x + be.x;
            o.y = rv.y + pv.y + be.y;
            o.z = rv.z + pv.z + be.z;
            o.w = rv.w + pv.w + be.w;
            *((float4*)(out + off.x + gcol) + colw) = o;
        }
        __syncthreads();   // protect tile before next group's STS
    }
}

extern "C" void kernel_launch(void* const* d_in, const int* in_sizes, int n_in,
                              void* d_out, int out_size)
{
    const float* X   = (const float*)d_in[0];
    const float* W1  = (const float*)d_in[1];
    const float* b1  = (const float*)d_in[2];
    const float* W2  = (const float*)d_in[3];
    const float* b2  = (const float*)d_in[4];
    const float* W3  = (const float*)d_in[5];
    const float* b3  = (const float*)d_in[6];
    const float* cls = (const float*)d_in[7];
    const float* pos = (const float*)d_in[8];
    float* out = (float*)d_out;

    cudaFuncSetAttribute(patch_embed_mma,
                         cudaFuncAttributeMaxDynamicSharedMemorySize, SMEMSZ);

    prep_kernel<<<96, 256>>>(W1, b1, W2, b2, W3, b3, cls, pos, out);
    patch_embed_mma<<<392, THREADS, SMEMSZ>>>(X, pos, out);
}

// round 15
// speedup vs baseline: 1.1147x; 1.0258x over previous
#include <cuda_runtime.h>
#include <cuda_bf16.h>
#include <cstdint>

// PatchEmbeder via mma.sync tf32 m16n8k8 + affine collapse.
// out[b,0,:]   = cls + pos[0]                                  (prep kernel)
// out[b,p+1,:] = x_patch @ W1 @ (W2@W3) + beff + pos[p+1]      (main kernel)
// x[b,p,k] = inputs[b, k/256, p, (k%256)/16, k%16]
// B=128, P=196 -> 25088 rows = 392 CTAs x 64 rows. K1=768, N1=32(=K2), E=768.
//
// R15: (1) prep W23 mapping reverted to R10 (e per warp, W3 loads are warp-
// uniform broadcasts = 1 sector; the R11 "coalesced" mapping multiplied W3
// traffic 32x and cost ~3us); (2) G1 inner loop software-pipelines the W1F
// fragment LDGs one gq ahead; rowbase pointers -> 32-bit offsets to pay the regs.

#define THREADS 128
#define RS2     272              // staging/result row stride bytes (68 words, ==4 mod 32)
#define BUF2    (16 * RS2)       // 4352 B per ring buffer
#define WSLOT   (2 * BUF2)       // 8704 B per warp (depth-2 ring)
#define HS      144              // H exchange row stride bytes (36 words)
#define HOFF    17408            // H buffer offset (after 64*272 result tile)
#define OFFO    34816            // row-offset table (dedicated, after rings)
#define SMEMSZ  35328

// ---- device scratch (rebuilt every replay by prep_kernel) ----
__device__ __align__(16) uint4 g_W1F [48 * 4 * 32];   // [kt16 48][nt 4][lane]
__device__ __align__(16) uint4 g_W23F[96 * 2 * 32];   // [nt 96][kt8-pair 2][lane]
__device__ __align__(16) float g_beff[768];

__device__ __forceinline__ uint32_t f2tf32(float f) {
    uint32_t r;
    asm("cvt.rna.tf32.f32 %0, %1;" : "=r"(r) : "f"(f));
    return r;
}
__device__ __forceinline__ void mma_tf32(float* c, const uint32_t a[4],
                                         uint32_t b0, uint32_t b1) {
    asm("mma.sync.aligned.m16n8k8.row.col.f32.tf32.tf32.f32 "
        "{%0,%1,%2,%3}, {%4,%5,%6,%7}, {%8,%9}, {%0,%1,%2,%3};"
        : "+f"(c[0]), "+f"(c[1]), "+f"(c[2]), "+f"(c[3])
        : "r"(a[0]), "r"(a[1]), "r"(a[2]), "r"(a[3]), "r"(b0), "r"(b1));
}
__device__ __forceinline__ uint32_t smem_u32(const void* p) {
    uint32_t a;
    asm("{ .reg .u64 t; cvta.to.shared.u64 t, %1; cvt.u32.u64 %0, t; }" : "=r"(a) : "l"(p));
    return a;
}
__device__ __forceinline__ void cp_async16(uint32_t dst, const void* src) {
    asm volatile("cp.async.cg.shared.global [%0], [%1], 16;" :: "r"(dst), "l"(src));
}
#define CP_COMMIT()  asm volatile("cp.async.commit_group;" ::: "memory")
#define CP_WAIT(N)   asm volatile("cp.async.wait_group %0;" :: "n"(N) : "memory")
__device__ __forceinline__ float lds32(uint32_t a) {
    float v;
    asm volatile("ld.shared.f32 %0, [%1];" : "=f"(v) : "r"(a));
    return v;
}
__device__ __forceinline__ void sts64(uint32_t a, float x, float y) {
    asm volatile("st.shared.v2.f32 [%0], {%1,%2};" :: "r"(a), "f"(x), "f"(y));
}
__device__ __forceinline__ void sts64i(uint32_t a, int x, int y) {
    asm volatile("st.shared.v2.u32 [%0], {%1,%2};" :: "r"(a), "r"(x), "r"(y));
}
__device__ __forceinline__ int2 lds64i(uint32_t a) {
    int2 v;
    asm volatile("ld.shared.v2.u32 {%0,%1}, [%2];" : "=r"(v.x), "=r"(v.y) : "r"(a));
    return v;
}
__device__ __forceinline__ float4 lds128(uint32_t a) {
    float4 v;
    asm volatile("ld.shared.v4.f32 {%0,%1,%2,%3}, [%4];"
                 : "=f"(v.x), "=f"(v.y), "=f"(v.z), "=f"(v.w) : "r"(a));
    return v;
}

// =====================================================================
// prep: bake W1 / W23=W2@W3 tf32 fragments, beff, cls rows.
// grid 96 x 256 = 24576 threads. W23 mapping: one e-column per warp
// (k2 in lanes) -> W3 loads are warp-uniform broadcasts (1 sector each),
// and each W3 element is read by exactly one warp.
// =====================================================================
__global__ void prep_kernel(const float* __restrict__ W1, const float* __restrict__ b1,
                            const float* __restrict__ W2, const float* __restrict__ b2,
                            const float* __restrict__ W3, const float* __restrict__ b3,
                            const float* __restrict__ cls, const float* __restrict__ pos,
                            float* __restrict__ out)
{
    __shared__ float W2s[32 * 65];   // padded stride 65
    __shared__ float t1s[64];

    const int t = threadIdx.x;
    const int g = blockIdx.x * 256 + t;   // 0..24575

#pragma unroll
    for (int i = t; i < 2048; i += 256)
        W2s[(i >> 6) * 65 + (i & 63)] = __ldg(W2 + i);
    __syncthreads();

    if (t < 64) {
        float acc = __ldg(b2 + t);
#pragma unroll
        for (int i = 0; i < 32; ++i) acc += __ldg(b1 + i) * W2s[i * 65 + t];
        t1s[t] = acc;
    }
    __syncthreads();

    // ---- W1 fragment element (k = g>>5 in 0..767, n = g&31) ----
    {
        const int k = g >> 5, n = g & 31;
        const uint32_t tv = f2tf32(__ldg(W1 + k * 32 + n));
        const int kt16 = k >> 4;
        const int comp = (((k >> 3) & 1) << 1) | ((k & 7) >> 2);
        const int lane = ((n & 7) << 2) | (k & 3);
        const int nt = n >> 3;
        ((uint32_t*)&g_W1F[(kt16 * 4 + nt) * 32 + lane])[comp] = tv;
    }
    // ---- W23 fragment + beff: (e = g>>5, k2 = g&31) — R10 mapping ----
    {
        const int e = g >> 5, k2 = g & 31;
        float acc = 0.f;
        float accb = (k2 == 0) ? __ldg(b3 + e) : 0.f;
#pragma unroll
        for (int j = 0; j < 64; ++j) {
            const float w3v = __ldg(W3 + j * 768 + e);   // warp-uniform broadcast
            acc += W2s[k2 * 65 + j] * w3v;
            if (k2 == 0) accb += t1s[j] * w3v;
        }
        const uint32_t tv = f2tf32(acc);
        const int nt = e >> 3, pair = k2 >> 4;
        const int comp = (((k2 >> 3) & 1) << 1) | ((k2 & 7) >> 2);
        const int lane = ((e & 7) << 2) | (k2 & 3);
        ((uint32_t*)&g_W23F[(nt * 2 + pair) * 32 + lane])[comp] = tv;
        if (k2 == 0) g_beff[e] = accb;
    }
    // ---- cls rows ----
    {
        const int e4 = g % 192, b = g / 192;
        const float4 c = __ldg((const float4*)cls + e4);
        const float4 pp = __ldg((const float4*)pos + e4);
        *((float4*)(out + (size_t)b * 197 * 768) + e4) =
            make_float4(c.x + pp.x, c.y + pp.y, c.z + pp.z, c.w + pp.w);
    }
}

// =====================================================================
// main: 392 CTAs x 128 threads (4 warps), 64 rows.
// G1: warp-private depth-2 cp.async ring of 64-col fp32 X chunks; W1F
//     fragment LDGs software-pipelined one gq ahead.
// G23: H exchanged via smem; each warp holds A-frags for ALL 64 rows;
//      12 groups of 64 cols, 2 n-tiles per warp per group.
// =====================================================================
__global__ __launch_bounds__(THREADS, 3)
void patch_embed_mma(const float* __restrict__ X, const float* __restrict__ pos,
                     float* __restrict__ out)
{
    extern __shared__ char smem[];
    const uint32_t sb = smem_u32(smem);
    const int t = threadIdx.x;
    const int w = t >> 5;
    const int ln = t & 31;
    const int r0 = blockIdx.x * 64;
    const int wr0 = w << 4;                       // warp's 16 rows (G1 / write-out)
    const uint32_t wbuf = sb + (uint32_t)w * WSLOT;

    const int gr = ln >> 2;                       // fragment row 0..7
    const int q2 = (ln & 3) << 1;                 // C-fragment col pair base

    // per-row gmem element offsets (32-bit) for this warp's 16 G1 rows
    uint32_t rowoff[16];
#pragma unroll
    for (int lr = 0; lr < 16; ++lr) {
        const int R = r0 + wr0 + lr;
        const int b = R / 196;
        const int p = R - b * 196;
        rowoff[lr] = (uint32_t)((b * 3 * 196 + p) << 8);
    }

    // ---------------- G1: H[16x32] = Xrows @ W1, tf32, depth-2 ring ----------------
    float acc1[4][4];
#pragma unroll
    for (int i = 0; i < 4; ++i)
#pragma unroll
        for (int j = 0; j < 4; ++j) acc1[i][j] = 0.f;

    // stage 64-col chunk kc (0..11) into ring slot d
    auto stage = [&](int kc, int d) {
        const uint32_t choff = (uint32_t)(kc >> 2) * (196u << 8) + ((kc & 3) << 6)
                             + ((ln & 15) << 2);
        const uint32_t dst = wbuf + (uint32_t)d * BUF2 + (uint32_t)((ln & 15) << 4);
        const int lr0 = ln >> 4;
#pragma unroll
        for (int it = 0; it < 8; ++it) {
            const int lr = (it << 1) + lr0;
            cp_async16(dst + (uint32_t)lr * RS2, X + rowoff[lr] + choff);
        }
        CP_COMMIT();
    };

    auto consume = [&](int kc, int d) {
        const uint32_t a0 = wbuf + (uint32_t)d * BUF2 + (uint32_t)gr * RS2
                          + (uint32_t)((ln & 3) << 2);
        // prefetch gq=0 B fragments
        uint4 bf[4];
        {
            const uint4* bp = &g_W1F[(kc << 4) * 32 + ln];
#pragma unroll
            for (int nt = 0; nt < 4; ++nt) bf[nt] = __ldg(bp + nt * 32);
        }
#pragma unroll
        for (int gq = 0; gq < 4; ++gq) {            // 4 kt16-groups per 64-col chunk
            uint4 bn[4];
            if (gq < 3) {                           // prefetch next gq's B fragments
                const uint4* bq = &g_W1F[(((kc << 2) + gq + 1) << 2) * 32 + ln];
#pragma unroll
                for (int nt = 0; nt < 4; ++nt) bn[nt] = __ldg(bq + nt * 32);
            }
            const uint32_t ae = a0 + (uint32_t)(gq << 6);
            uint32_t Ae[4], Ao[4];
            Ae[0] = f2tf32(lds32(ae));
            Ae[1] = f2tf32(lds32(ae + 8 * RS2));
            Ae[2] = f2tf32(lds32(ae + 16));
            Ae[3] = f2tf32(lds32(ae + 8 * RS2 + 16));
            Ao[0] = f2tf32(lds32(ae + 32));
            Ao[1] = f2tf32(lds32(ae + 8 * RS2 + 32));
            Ao[2] = f2tf32(lds32(ae + 48));
            Ao[3] = f2tf32(lds32(ae + 8 * RS2 + 48));

#pragma unroll
            for (int nt = 0; nt < 4; ++nt) mma_tf32(acc1[nt], Ae, bf[nt].x, bf[nt].y);
#pragma unroll
            for (int nt = 0; nt < 4; ++nt) mma_tf32(acc1[nt], Ao, bf[nt].z, bf[nt].w);
#pragma unroll
            for (int nt = 0; nt < 4; ++nt) bf[nt] = bn[nt];
        }
    };

    stage(0, 0);
#pragma unroll
    for (int c = 0; c < 12; ++c) {
        if (c < 11) { stage(c + 1, (c + 1) & 1); CP_WAIT(1); }
        else        { CP_WAIT(0); }
        __syncwarp();
        consume(c, c & 1);
    }

    // ---------------- exchange H through smem (rings dead after this sync) ---------
    __syncthreads();
    {
        const uint32_t hb = sb + HOFF + (uint32_t)(wr0 + gr) * HS + (uint32_t)(q2 << 2);
#pragma unroll
        for (int nt = 0; nt < 4; ++nt) {
            sts64(hb + (uint32_t)(nt << 5),          acc1[nt][0], acc1[nt][1]);
            sts64(hb + (uint32_t)(nt << 5) + 8 * HS, acc1[nt][2], acc1[nt][3]);
        }
    }
    // row-offset table for all 64 rows (out offset, pos offset)
    if (t < 64) {
        const int R = r0 + t;
        const int b = R / 196;
        const int p = R - b * 196;
        sts64i(sb + OFFO + (t << 3), (b * 197 + p + 1) * 768, (p + 1) * 768);
    }
    __syncthreads();

    // ---------------- A-fragments for ALL 64 rows (tf32, from smem H) --------------
    uint32_t Afr[4][4][4];   // [row-block][kq][reg]
    {
        const uint32_t hb = sb + HOFF + (uint32_t)((ln & 3) << 2);
#pragma unroll
        for (int rb = 0; rb < 4; ++rb) {
            const uint32_t base = hb + (uint32_t)(rb * 16 + gr) * HS;
#pragma unroll
            for (int q = 0; q < 4; ++q) {
                Afr[rb][q][0] = f2tf32(lds32(base + (q << 5)));
                Afr[rb][q][1] = f2tf32(lds32(base + (q << 5) + 8 * HS));
                Afr[rb][q][2] = f2tf32(lds32(base + (q << 5) + 16));
                Afr[rb][q][3] = f2tf32(lds32(base + (q << 5) + 16 + 8 * HS));
            }
        }
    }

    // ---------------- G23: 12 groups of 64 cols; 2 n-tiles/warp/group --------------
    const uint32_t res = sb;                      // result tile: 64 rows x 68 floats
    const int colw = ln & 15;                     // epilogue: lane's float4 column
    const int rowsel = ln >> 4;                   // epilogue: row within pair

    for (int gidx = 0; gidx < 12; ++gidx) {
        const int nt0 = gidx * 8 + w * 2;         // this warp's 2 tiles in the group
        uint4 p0 = __ldg(&g_W23F[((nt0 << 1) + 0) * 32 + ln]);
        uint4 p1 = __ldg(&g_W23F[((nt0 << 1) + 1) * 32 + ln]);
#pragma unroll
        for (int i = 0; i < 2; ++i) {
            uint4 n0, n1;
            if (i == 0) {
                n0 = __ldg(&g_W23F[(((nt0 + 1) << 1) + 0) * 32 + ln]);
                n1 = __ldg(&g_W23F[(((nt0 + 1) << 1) + 1) * 32 + ln]);
            }
            float c[4][4];
#pragma unroll
            for (int rb = 0; rb < 4; ++rb) {
                c[rb][0] = 0.f; c[rb][1] = 0.f; c[rb][2] = 0.f; c[rb][3] = 0.f;
            }
#pragma unroll
            for (int rb = 0; rb < 4; ++rb) {
                mma_tf32(c[rb], Afr[rb][0], p0.x, p0.y);
                mma_tf32(c[rb], Afr[rb][1], p0.z, p0.w);
                mma_tf32(c[rb], Afr[rb][2], p1.x, p1.y);
                mma_tf32(c[rb], Afr[rb][3], p1.z, p1.w);
            }
            // store: cols ((w*2+i)*8 + q2) of the 64-col group
            const uint32_t cb = res + (uint32_t)(((w << 1) + i) << 5) + (uint32_t)(q2 << 2);
#pragma unroll
            for (int rb = 0; rb < 4; ++rb) {
                const uint32_t ra = cb + (uint32_t)(rb * 16 + gr) * RS2;
                sts64(ra,           c[rb][0], c[rb][1]);
                sts64(ra + 8 * RS2, c[rb][2], c[rb][3]);
            }
            p0 = n0; p1 = n1;
        }
        __syncthreads();

        // cooperative write-out: warp w writes rows [w*16, w*16+16), 2 rows/iter
        const int gcol = gidx * 64;
        const float4 be = __ldg((const float4*)(g_beff + gcol) + colw);
#pragma unroll
        for (int it = 0; it < 8; ++it) {
            const int row = wr0 + (it << 1) + rowsel;
            const int2 off = lds64i(sb + OFFO + (row << 3));
            const float4 rv = lds128(res + (uint32_t)row * RS2 + (uint32_t)(colw << 4));
            const float4 pv = __ldg((const float4*)(pos + off.y + gcol) + colw);
            float4 o;
            o.x = rv.x + pv.x + be.x;
            o.y = rv.y + pv.y + be.y;
            o.z = rv.z + pv.z + be.z;
            o.w = rv.w + pv.w + be.w;
            *((float4*)(out + off.x + gcol) + colw) = o;
        }
        __syncthreads();   // protect tile before next group's STS
    }
}

extern "C" void kernel_launch(void* const* d_in, const int* in_sizes, int n_in,
                              void* d_out, int out_size)
{
    const float* X   = (const float*)d_in[0];
    const float* W1  = (const float*)d_in[1];
    const float* b1  = (const float*)d_in[2];
    const float* W2  = (const float*)d_in[3];
    const float* b2  = (const float*)d_in[4];
    const float* W3  = (const float*)d_in[5];
    const float* b3  = (const float*)d_in[6];
    const float* cls = (const float*)d_in[7];
    const float* pos = (const float*)d_in[8];
    float* out = (float*)d_out;

    cudaFuncSetAttribute(patch_embed_mma,
                         cudaFuncAttributeMaxDynamicSharedMemorySize, SMEMSZ);

    prep_kernel<<<96, 256>>>(W1, b1, W2, b2, W3, b3, cls, pos, out);
    patch_embed_mma<<<392, THREADS, SMEMSZ>>>(X, pos, out);
}